// round 12
// baseline (speedup 1.0000x reference)
#include <cuda_runtime.h>

typedef unsigned long long ull;
#define HST 132   // smem row stride for X / hq / hd (conflict-free .128)

__device__ float g_hq[64 * 64 * 128];   // [b][j][h], j = compacted valid-n index
__device__ float g_hd[64 * 64 * 128];   // [b][j][h], j = compacted valid-m index

// ---- f32x2 packed helpers ----
__device__ __forceinline__ ull pack2(float x, float y) {
    ull r; asm("mov.b64 %0, {%1,%2};" : "=l"(r) : "f"(x), "f"(y)); return r;
}
__device__ __forceinline__ void unpack2(ull v, float& x, float& y) {
    asm("mov.b64 {%0,%1}, %2;" : "=f"(x), "=f"(y) : "l"(v));
}
__device__ __forceinline__ ull fma2(ull a, ull b, ull c) {
    ull d; asm("fma.rn.f32x2 %0, %1, %2, %3;" : "=l"(d) : "l"(a), "l"(b), "l"(c)); return d;
}
__device__ __forceinline__ ull add2(ull a, ull b) {
    ull d; asm("add.rn.f32x2 %0, %1, %2;" : "=l"(d) : "l"(a), "l"(b)); return d;
}

// Mask dtype: 0 = int32, 1 = uint8, 2 = float32
__device__ __forceinline__ bool mask_at(const void* p, int i, int mode) {
    if (mode == 0) return ((const int*)p)[i] != 0;
    if (mode == 2) return ((const float*)p)[i] != 0.0f;
    return ((const unsigned char*)p)[i] != 0;
}

// In-warp mask dtype detection (registers only)
__device__ __forceinline__ int detect_mode(const void* qmask, int lane) {
    const unsigned* qw = (const unsigned*)qmask;
    int notInt = 0, notF32 = 0;
    for (int i = lane; i < 512; i += 32) {
        unsigned w = qw[i];
        notInt |= (w > 1u) ? 1 : 0;
        notF32 |= (w != 0u && w != 0x3F800000u) ? 1 : 0;
    }
    notInt = __any_sync(0xFFFFFFFFu, notInt);
    notF32 = __any_sync(0xFFFFFFFFu, notF32);
    return (!notInt) ? 0 : ((!notF32) ? 2 : 1);
}

// ============================================================================
// Proj: grid = 512 = (b, side, hslice32). 256 threads, ~50KB smem, 4 blk/SM.
// Computes compacted h-rows for a 32-wide h slice; broadcast-W warp mapping.
// ============================================================================
__global__ void __launch_bounds__(256)
proj_kernel(const float* __restrict__ query, const float* __restrict__ doc,
            const void* __restrict__ qmask, const void* __restrict__ dmask,
            const float* __restrict__ W1, const float* __restrict__ b1)
{
    extern __shared__ float sm[];
    float* Wsl = sm;                    // [128][32]  W1 slice
    float* Xs  = Wsl + 128 * 32;        // [64][HST]
    float* b1s = Xs + 64 * HST;         // [32]
    int* list  = (int*)(b1s + 32);      // 64
    int* meta  = list + 64;             // [0]=cnt

    const int tid  = threadIdx.x;
    const int lane = tid & 31;
    const int wid  = tid >> 5;
    const int b    = blockIdx.x >> 3;
    const int side = (blockIdx.x >> 2) & 1;
    const int hs4  = blockIdx.x & 3;    // 32-h slice

    if (wid == 0) {
        const int mode = detect_mode(qmask, lane);
        const void* mp = side ? dmask : qmask;
        const unsigned lt = (1u << lane) - 1u;
        bool v0 = mask_at(mp, b * 64 + lane, mode);
        unsigned m0 = __ballot_sync(0xFFFFFFFFu, v0);
        bool v1 = mask_at(mp, b * 64 + 32 + lane, mode);
        unsigned m1 = __ballot_sync(0xFFFFFFFFu, v1);
        int c0 = __popc(m0);
        if (v0) list[__popc(m0 & lt)] = lane;
        if (v1) list[c0 + __popc(m1 & lt)] = 32 + lane;
        if (lane == 0) meta[0] = c0 + __popc(m1);
        b1s[lane] = (side == 0) ? b1[hs4 * 32 + lane] : 0.0f;
    } else {
        // stage W1 slice: rows d 0..127, cols hs4*32..+32  (1024 float4)
        const float* Wg = W1 + side * 16384 + hs4 * 32;
        for (int i = tid - 32; i < 1024; i += 224) {
            int d = i >> 3, c4 = i & 7;
            *(float4*)(Wsl + d * 32 + c4 * 4) = *(const float4*)(Wg + d * 128 + c4 * 4);
        }
    }
    __syncthreads();

    const int cnt = meta[0];
    if (cnt == 0) return;

    // stage compacted X rows
    const float* X = (side ? doc : query) + (size_t)b * 8192;
    for (int i = tid; i < cnt * 32; i += 256) {
        int r = i >> 5, seg = i & 31;
        *(float4*)(Xs + r * HST + seg * 4) =
            ((const float4*)(X + list[r] * 128))[seg];
    }
    __syncthreads();

    // compute: warp job = 16 rows x 16 h (lane = 1 row x 8 h)
    const int rg  = wid >> 1;                    // 0..3 rowgroup
    const int row = rg * 16 + (lane & 15);
    const int h0  = (wid & 1) * 16 + (lane >> 4) * 8;
    if (rg * 16 >= cnt) return;

    ull a0 = 0, a1 = 0, a2 = 0, a3 = 0;
    const float* xr = Xs + row * HST;
#pragma unroll 4
    for (int d4 = 0; d4 < 32; d4++) {
        float4 x4 = *(const float4*)(xr + 4 * d4);
        const float* wp = Wsl + d4 * 128;        // 4 d-rows of 32
        float xs[4] = {x4.x, x4.y, x4.z, x4.w};
#pragma unroll
        for (int k = 0; k < 4; k++) {
            ull px = pack2(xs[k], xs[k]);
            ulonglong2 wA = *(const ulonglong2*)(wp + k * 32 + h0);
            ulonglong2 wB = *(const ulonglong2*)(wp + k * 32 + h0 + 4);
            a0 = fma2(px, wA.x, a0); a1 = fma2(px, wA.y, a1);
            a2 = fma2(px, wB.x, a2); a3 = fma2(px, wB.y, a3);
        }
    }
    if (row < cnt) {
        float* g = (side ? g_hd : g_hq) + ((size_t)(b * 64 + row) * 128) + hs4 * 32 + h0;
        float4 bA = *(const float4*)(b1s + h0);
        float4 bB = *(const float4*)(b1s + h0 + 4);
        float v0, v1, v2, v3;
        unpack2(a0, v0, v1); unpack2(a1, v2, v3);
        *(float4*)g = make_float4(v0 + bA.x, v1 + bA.y, v2 + bA.z, v3 + bA.w);
        unpack2(a2, v0, v1); unpack2(a3, v2, v3);
        *(float4*)(g + 4) = make_float4(v0 + bB.x, v1 + bB.y, v2 + bB.z, v3 + bB.w);
    }
}

// ============================================================================
// Pair: grid = 256 = (b, n-half, m-half). 256 threads.
// 1 PAIR PER THREAD (no tiles): all threads active, short dep chains.
// Window-valid rows are a contiguous run of the full compacted list.
// ============================================================================
__global__ void __launch_bounds__(256)
pair_kernel(const void* __restrict__ qmask, const void* __restrict__ dmask,
            const float* __restrict__ W2g, const float* __restrict__ b2g,
            float* __restrict__ out)
{
    extern __shared__ float sm[];
    float* hq_s = sm;                   // [32][HST]
    float* hd_s = hq_s + 32 * HST;      // [32][HST]
    float* w2_s = hd_s + 32 * HST;      // [3][128]
    int* wnlist = (int*)(w2_s + 384);   // 32 (local n in window)
    int* wmlist = wnlist + 32;          // 32
    int* meta   = wmlist + 32;          // [0]=qstart [1]=qcnt [2]=mstart [3]=mcnt

    const int tid  = threadIdx.x;
    const int lane = tid & 31;
    const int wid  = tid >> 5;
    const int b    = blockIdx.x >> 2;
    const int nh   = (blockIdx.x >> 1) & 1;
    const int mh   = blockIdx.x & 1;

    // zero-fill own 32n x 32m x 3 window
    float* obase = out + (size_t)((b * 64 + nh * 32) * 64 + mh * 32) * 3;
    {
        float4 z = make_float4(0.f, 0.f, 0.f, 0.f);
        for (int i = tid; i < 768; i += 256) {
            int r = i / 24, c = i - r * 24;
            ((float4*)(obase + r * 192))[c] = z;
        }
    }

    if (wid == 0 || wid == 1) {
        const int mode = detect_mode(qmask, lane);
        const void* mp = (wid == 0) ? qmask : dmask;
        const int hh   = (wid == 0) ? nh : mh;
        int* wlist     = (wid == 0) ? wnlist : wmlist;
        const unsigned lt = (1u << lane) - 1u;
        bool v0 = mask_at(mp, b * 64 + lane, mode);
        unsigned m0 = __ballot_sync(0xFFFFFFFFu, v0);
        bool v1 = mask_at(mp, b * 64 + 32 + lane, mode);
        unsigned m1 = __ballot_sync(0xFFFFFFFFu, v1);
        unsigned win = hh ? m1 : m0;
        bool inwin = hh ? v1 : v0;
        if (inwin) wlist[__popc(win & lt)] = lane;
        if (lane == 0) {
            meta[(wid == 0) ? 0 : 2] = hh ? __popc(m0) : 0;   // start in run
            meta[(wid == 0) ? 1 : 3] = __popc(win);           // cnt
        }
    } else if (wid == 2 || wid == 3) {
        for (int i = tid - 64; i < 384; i += 64) {            // W2 -> [o][h]
            int h = i / 3, o = i - h * 3;
            w2_s[o * 128 + h] = W2g[i];
        }
    }
    __syncthreads();

    const int qstart = meta[0], qcnt = meta[1];
    const int mstart = meta[2], mcnt = meta[3];
    if (qcnt == 0 || mcnt == 0) return;

    // stage window hq/hd rows (exact counts)
    for (int i = tid; i < qcnt * 32; i += 256) {
        int r = i >> 5, seg = i & 31;
        *(float4*)(hq_s + r * HST + seg * 4) =
            ((const float4*)(g_hq + (size_t)(b * 64 + qstart + r) * 128))[seg];
    }
    for (int i = tid; i < mcnt * 32; i += 256) {
        int r = i >> 5, seg = i & 31;
        *(float4*)(hd_s + r * HST + seg * 4) =
            ((const float4*)(g_hd + (size_t)(b * 64 + mstart + r) * 128))[seg];
    }
    __syncthreads();

    // ---- 1 pair per thread; consecutive lanes share ni -> A near-broadcast
    const int total = qcnt * mcnt;
    const float b2_0 = b2g[0], b2_1 = b2g[1], b2_2 = b2g[2];

    for (int t = tid; t < total; t += 256) {
        const int ni = t / mcnt;
        const int mi = t - ni * mcnt;
        const float* pa = hq_s + ni * HST;
        const float* pd = hd_s + mi * HST;

        ull a0 = 0, a1 = 0, a2 = 0;
#pragma unroll 4
        for (int h = 0; h < 128; h += 4) {
            ulonglong2 A = *(const ulonglong2*)(pa + h);
            ulonglong2 D = *(const ulonglong2*)(pd + h);
            ull tlo = add2(A.x, D.x);
            ull thi = add2(A.y, D.y);
            float f0, f1, f2, f3;
            unpack2(tlo, f0, f1); unpack2(thi, f2, f3);
            f0 = fmaxf(f0, 0.f); f1 = fmaxf(f1, 0.f);
            f2 = fmaxf(f2, 0.f); f3 = fmaxf(f3, 0.f);
            tlo = pack2(f0, f1); thi = pack2(f2, f3);
            ulonglong2 w0  = *(const ulonglong2*)(w2_s + h);
            ulonglong2 w1  = *(const ulonglong2*)(w2_s + 128 + h);
            ulonglong2 w2v = *(const ulonglong2*)(w2_s + 256 + h);
            a0 = fma2(tlo, w0.x,  a0); a0 = fma2(thi, w0.y,  a0);
            a1 = fma2(tlo, w1.x,  a1); a1 = fma2(thi, w1.y,  a1);
            a2 = fma2(tlo, w2v.x, a2); a2 = fma2(thi, w2v.y, a2);
        }

        const int gn = wnlist[ni], gm = wmlist[mi];
        float lo, hi;
        float* po = obase + gn * 192 + gm * 3;
        unpack2(a0, lo, hi); po[0] = lo + hi + b2_0;
        unpack2(a1, lo, hi); po[1] = lo + hi + b2_1;
        unpack2(a2, lo, hi); po[2] = lo + hi + b2_2;
    }
}

// ============================================================================
extern "C" void kernel_launch(void* const* d_in, const int* in_sizes, int n_in,
                              void* d_out, int out_size)
{
    const float* query = (const float*)d_in[0];
    const float* doc   = (const float*)d_in[1];
    const void*  qmask = d_in[2];
    const void*  dmask = d_in[3];
    const float* W1    = (const float*)d_in[4];
    const float* b1    = (const float*)d_in[5];
    const float* W2    = (const float*)d_in[6];
    const float* b2    = (const float*)d_in[7];
    float* out = (float*)d_out;

    const int sm1 = (128 * 32 + 64 * HST + 32) * (int)sizeof(float)
                    + (64 + 1) * (int)sizeof(int);             // ~50.6 KB
    const int sm2 = (32 * HST * 2 + 384) * (int)sizeof(float)
                    + (32 + 32 + 4) * (int)sizeof(int);        // ~35.6 KB

    cudaFuncSetAttribute(proj_kernel, cudaFuncAttributeMaxDynamicSharedMemorySize, sm1);
    cudaFuncSetAttribute(pair_kernel, cudaFuncAttributeMaxDynamicSharedMemorySize, sm2);

    proj_kernel<<<512, 256, sm1>>>(query, doc, qmask, dmask, W1, b1);
    pair_kernel<<<256, 256, sm2>>>(qmask, dmask, W2, b2, out);
}